// round 14
// baseline (speedup 1.0000x reference)
#include <cuda_runtime.h>
#include <cstdint>

// Decoder_2430951489916 — v14: v13 + short-chain zw reduce (3-deep SHFL,
// 32-lane parallel cluster-store fan-out) + sigma vote off the critical path.
//   B=4, N=512, M=512, ZD=128, YD=2, XD=1
// out[b,m,y] = b_y + sum_n sum_c W[y,c]*z[b,n,c]*exp(-0.5*((x_m-t_n)*exp(-sigma_c))^2)
// Fast path (uniform sigma, true for bench):
//   out[b,m,y] = b_y + sum_n exp(coef*(x_m-t_n)^2) * zw[b,n,y],  zw = z @ W^T.
//
// 16 clusters x 8 CTAs, 512 threads. zw phase: each warp owns 4 z-rows as
// 4 rows x 8 lane-segments (lane L -> row nbase+(L>>3), channels (L&7)*16..);
// 3-deep xor(1,2,4) group reduce; then EVERY lane does one st.shared::cluster
// (its row -> rank L&7): 4 rows x 8 ranks = 32 stores, fully lane-parallel.
// Exps overlap z latency; one cluster arrive+wait; epilogue 32 FMA + warp
// reduce + STG.64. No CTA barriers, no global atomics.

#define BB 4
#define NN 512
#define MM 512
#define ZDIM 128
#define CLUSTER 8
#define NTHREADS 512
#define GRID (BB * 4 * CLUSTER)      // 128 CTAs = 16 clusters

typedef unsigned long long u64;

__device__ __forceinline__ uint32_t smem_u32(const void* p) {
    uint32_t a;
    asm("{ .reg .u64 tt; cvta.to.shared.u64 tt, %1; cvt.u32.u64 %0, tt; }"
        : "=r"(a) : "l"(p));
    return a;
}
__device__ __forceinline__ void st_cluster_f2(uint32_t addr, uint32_t rank,
                                              float a, float b) {
    u64 v; asm("mov.b64 %0,{%1,%2};" : "=l"(v) : "f"(a), "f"(b));
    uint32_t r;
    asm("mapa.shared::cluster.u32 %0, %1, %2;" : "=r"(r) : "r"(addr), "r"(rank));
    asm volatile("st.shared::cluster.b64 [%0], %1;" :: "r"(r), "l"(v) : "memory");
}

__global__ void __launch_bounds__(NTHREADS) __cluster_dims__(CLUSTER, 1, 1)
decoder_v14(const float* __restrict__ t,
            const float* __restrict__ z,
            const float* __restrict__ x,
            const float* __restrict__ sigma,
            const float* __restrict__ W,
            const float* __restrict__ bias,
            float* __restrict__ out) {
    __shared__ float2 zw_s[NN];      // full batch zw (peer-filled)

    const int tid  = threadIdx.x;
    const int w    = tid >> 5;       // 16 warps -> 16 m-points per CTA
    const int lane = tid & 31;
    uint32_t rank;
    asm("mov.u32 %0, %%cluster_ctarank;" : "=r"(rank));
    const int cl = blockIdx.x >> 3;          // cluster id 0..15
    const int b  = cl >> 2;                  // batch
    const int mq = cl & 3;                   // m-quarter
    const int m  = mq * 128 + (int)rank * 16 + w;

    // zw-phase lane mapping: 4 rows x 8 segments
    const int rsub = lane >> 3;              // 0..3  : row within warp's 4
    const int seg  = lane & 7;               // 0..7  : 16-channel segment
    const int nbase = (int)rank * 64 + w * 4;
    const int nrow  = nbase + rsub;

    // ---- issue all long-latency loads up front ----
    const float xm = __ldg(x + b * MM + m);          // XD == 1, warp-uniform
    const float b0 = __ldg(bias + 0);
    const float b1 = __ldg(bias + 1);
    const float s0 = __ldg(sigma);

    const float4* zr = (const float4*)(z + (size_t)(b * NN + nrow) * ZDIM) + seg * 4;
    float4 zv[4];
#pragma unroll
    for (int j = 0; j < 4; ++j) zv[j] = __ldg(zr + j);
    float4 w0v[4], w1v[4];
#pragma unroll
    for (int j = 0; j < 4; ++j) {
        w0v[j] = __ldg((const float4*)W + seg * 4 + j);
        w1v[j] = __ldg((const float4*)W + 32 + seg * 4 + j);
    }

    // ---- exps overlap the z loads (depend only on t, x, sigma) ----
    const float coef = -0.5f * __expf(-2.0f * s0);
    const float* tg  = t + b * NN;
    float e[16];
#pragma unroll
    for (int k = 0; k < 16; ++k) {
        const float d = xm - __ldg(tg + 32 * k + lane);
        e[k] = __expf(coef * d * d);
    }

    // ---- zw: 32 FMA/lane, 3-deep group reduce, 32-lane parallel fan-out ----
    {
        float a0 = 0.f, a1 = 0.f;
#pragma unroll
        for (int j = 0; j < 4; ++j) {
            a0 = fmaf(zv[j].x, w0v[j].x, a0); a0 = fmaf(zv[j].y, w0v[j].y, a0);
            a0 = fmaf(zv[j].z, w0v[j].z, a0); a0 = fmaf(zv[j].w, w0v[j].w, a0);
            a1 = fmaf(zv[j].x, w1v[j].x, a1); a1 = fmaf(zv[j].y, w1v[j].y, a1);
            a1 = fmaf(zv[j].z, w1v[j].z, a1); a1 = fmaf(zv[j].w, w1v[j].w, a1);
        }
#pragma unroll
        for (int o = 1; o < 8; o <<= 1) {            // xor 1,2,4 within 8-lane group
            a0 += __shfl_xor_sync(0xFFFFFFFFu, a0, o);
            a1 += __shfl_xor_sync(0xFFFFFFFFu, a1, o);
        }
        // every lane: its group's row -> cluster rank (lane&7)
        st_cluster_f2(smem_u32(zw_s) + (uint32_t)nrow * 8u, (uint32_t)seg, a0, a1);
    }

    // ---- sigma vote off the critical path (gates only post-barrier code) ----
    bool diffp = false;
#pragma unroll
    for (int j = 0; j < 4; ++j)
        diffp |= (__ldg(sigma + lane + 32 * j) != s0);
    const int nonuniform = __any_sync(0xFFFFFFFFu, diffp);   // warp-uniform

    // ---- cluster barrier: orders all CTAs' DSMEM stores ----
    asm volatile("barrier.cluster.arrive.aligned;" ::: "memory");
    asm volatile("barrier.cluster.wait.aligned;"  ::: "memory");

    float s_0, s_1;
    if (!nonuniform) {
        float p0 = 0.f, q0 = 0.f, p1 = 0.f, q1 = 0.f;
#pragma unroll
        for (int k = 0; k < 16; k += 2) {
            const float2 wa = zw_s[32 * k + lane];
            const float2 wb = zw_s[32 * (k + 1) + lane];
            p0 = fmaf(e[k],     wa.x, p0);  p1 = fmaf(e[k],     wa.y, p1);
            q0 = fmaf(e[k + 1], wb.x, q0);  q1 = fmaf(e[k + 1], wb.y, q1);
        }
        s_0 = p0 + q0;
        s_1 = p1 + q1;
    } else {
        // general path: per-channel length scales (correct for any sigma)
        s_0 = 0.f; s_1 = 0.f;
        float qv[4], wc0[4], wc1[4];
#pragma unroll
        for (int j = 0; j < 4; ++j) {
            const int c = lane + 32 * j;
            const float inv = __expf(-__ldg(sigma + c));
            qv[j]  = -0.5f * inv * inv;
            wc0[j] = __ldg(W + c);
            wc1[j] = __ldg(W + ZDIM + c);
        }
        for (int n = 0; n < NN; ++n) {
            const float d  = xm - __ldg(tg + n);
            const float d2 = d * d;
            const float* zrow = z + (size_t)(b * NN + n) * ZDIM;
#pragma unroll
            for (int j = 0; j < 4; ++j) {
                const float ev = __ldg(zrow + lane + 32 * j) * __expf(qv[j] * d2);
                s_0 = fmaf(ev, wc0[j], s_0);
                s_1 = fmaf(ev, wc1[j], s_1);
            }
        }
    }

    // ---- warp reduce + plain store (no atomics anywhere) ----
#pragma unroll
    for (int o = 16; o; o >>= 1) {
        s_0 += __shfl_xor_sync(0xFFFFFFFFu, s_0, o);
        s_1 += __shfl_xor_sync(0xFFFFFFFFu, s_1, o);
    }
    if (lane == 0)
        *(float2*)(out + 2 * (size_t)(b * MM + m)) = make_float2(s_0 + b0, s_1 + b1);
}

// ---------------------------------------------------------------------------
extern "C" void kernel_launch(void* const* d_in, const int* in_sizes, int n_in,
                              void* d_out, int out_size) {
    const float* t     = (const float*)d_in[0];
    const float* z     = (const float*)d_in[1];
    const float* x     = (const float*)d_in[2];
    const float* sigma = (const float*)d_in[3];
    const float* W     = (const float*)d_in[4];
    const float* bias  = (const float*)d_in[5];
    float* out = (float*)d_out;

    decoder_v14<<<GRID, NTHREADS>>>(t, z, x, sigma, W, bias, out);
}

// round 15
// speedup vs baseline: 1.2657x; 1.2657x over previous
#include <cuda_runtime.h>
#include <cstdint>

// Decoder_2430951489916 — FINAL (v13 configuration, best measured: 8.672us,
// reproduced across four structural variants; rounds 10/14 showed every
// further restructure regresses).
//   B=4, N=512, M=512, ZD=128, YD=2, XD=1
// out[b,m,y] = b_y + sum_n sum_c W[y,c]*z[b,n,c]*exp(-0.5*((x_m-t_n)*exp(-sigma_c))^2)
// Fast path (uniform sigma, true for bench):
//   out[b,m,y] = b_y + sum_n exp(coef*(x_m-t_n)^2) * zw[b,n,y],  zw = z @ W^T.
//
// 16 clusters x 8 CTAs, 512 threads. Each CTA builds zw for 64 n-rows
// (4 rows/warp; dense coalesced float4 z reads, warp-broadcast W) and
// broadcasts each row's float2 to all 8 cluster CTAs via mapa +
// st.shared::cluster (lanes 0-7 hit the 8 peers in parallel). Per-lane exps
// (depend only on t/x/sigma) overlap the z-load latency. One cluster
// arrive+wait orders the DSMEM stores; epilogue is 32 FMA + warp shuffle
// reduce + STG.64. Sigma-uniformity verdict via warp-local ballot — no
// __syncthreads, no global atomics anywhere.

#define BB 4
#define NN 512
#define MM 512
#define ZDIM 128
#define CLUSTER 8
#define NTHREADS 512
#define GRID (BB * 4 * CLUSTER)      // 128 CTAs = 16 clusters

typedef unsigned long long u64;

__device__ __forceinline__ uint32_t smem_u32(const void* p) {
    uint32_t a;
    asm("{ .reg .u64 tt; cvta.to.shared.u64 tt, %1; cvt.u32.u64 %0, tt; }"
        : "=r"(a) : "l"(p));
    return a;
}
__device__ __forceinline__ void st_cluster_f2(uint32_t addr, uint32_t rank,
                                              float a, float b) {
    u64 v; asm("mov.b64 %0,{%1,%2};" : "=l"(v) : "f"(a), "f"(b));
    uint32_t r;
    asm("mapa.shared::cluster.u32 %0, %1, %2;" : "=r"(r) : "r"(addr), "r"(rank));
    asm volatile("st.shared::cluster.b64 [%0], %1;" :: "r"(r), "l"(v) : "memory");
}

__global__ void __launch_bounds__(NTHREADS) __cluster_dims__(CLUSTER, 1, 1)
decoder_final(const float* __restrict__ t,
              const float* __restrict__ z,
              const float* __restrict__ x,
              const float* __restrict__ sigma,
              const float* __restrict__ W,
              const float* __restrict__ bias,
              float* __restrict__ out) {
    __shared__ float2 zw_s[NN];      // full batch zw (peer-filled)

    const int tid  = threadIdx.x;
    const int w    = tid >> 5;       // 16 warps -> 16 m-points per CTA
    const int lane = tid & 31;
    uint32_t rank;
    asm("mov.u32 %0, %%cluster_ctarank;" : "=r"(rank));
    const int cl = blockIdx.x >> 3;          // cluster id 0..15
    const int b  = cl >> 2;                  // batch
    const int mq = cl & 3;                   // m-quarter
    const int m  = mq * 128 + (int)rank * 16 + w;

    // ---- issue all long-latency loads up front ----
    const float  xm  = __ldg(x + b * MM + m);        // XD == 1, warp-uniform
    const float  b0  = __ldg(bias + 0);
    const float  b1  = __ldg(bias + 1);
    const float  s0  = __ldg(sigma);
    const float4 w0v = __ldg((const float4*)W + lane);
    const float4 w1v = __ldg((const float4*)W + 32 + lane);
    const int nbase = (int)rank * 64 + w * 4;        // this warp's 4 z rows
    float4 zv[4];
#pragma unroll
    for (int j = 0; j < 4; ++j)
        zv[j] = __ldg((const float4*)(z + (size_t)(b * NN + nbase + j) * ZDIM) + lane);

    // ---- warp-local sigma-uniformity vote (no CTA barrier needed) ----
    bool diff = false;
#pragma unroll
    for (int j = 0; j < 4; ++j)
        diff |= (__ldg(sigma + lane + 32 * j) != s0);
    const int nonuniform = __any_sync(0xFFFFFFFFu, diff);   // warp-uniform

    // ---- exps overlap the z loads (depend only on t, x, sigma) ----
    const float coef = -0.5f * __expf(-2.0f * s0);
    const float* tg  = t + b * NN;
    float e[16];
#pragma unroll
    for (int k = 0; k < 16; ++k) {
        const float d = xm - __ldg(tg + 32 * k + lane);
        e[k] = __expf(coef * d * d);
    }

    // ---- zw rows: dot + full shuffle reduce, broadcast to all 8 CTAs ----
    const uint32_t zw_base = smem_u32(zw_s);
#pragma unroll
    for (int j = 0; j < 4; ++j) {
        float a0 = zv[j].x * w0v.x;  a0 = fmaf(zv[j].y, w0v.y, a0);
        a0 = fmaf(zv[j].z, w0v.z, a0); a0 = fmaf(zv[j].w, w0v.w, a0);
        float a1 = zv[j].x * w1v.x;  a1 = fmaf(zv[j].y, w1v.y, a1);
        a1 = fmaf(zv[j].z, w1v.z, a1); a1 = fmaf(zv[j].w, w1v.w, a1);
#pragma unroll
        for (int o = 16; o; o >>= 1) {
            a0 += __shfl_xor_sync(0xFFFFFFFFu, a0, o);
            a1 += __shfl_xor_sync(0xFFFFFFFFu, a1, o);
        }
        if (lane < CLUSTER)
            st_cluster_f2(zw_base + (uint32_t)(nbase + j) * 8u, (uint32_t)lane, a0, a1);
    }

    // ---- cluster barrier: orders all CTAs' DSMEM stores ----
    asm volatile("barrier.cluster.arrive.aligned;" ::: "memory");
    asm volatile("barrier.cluster.wait.aligned;"  ::: "memory");

    float s_0, s_1;
    if (!nonuniform) {
        float p0 = 0.f, q0 = 0.f, p1 = 0.f, q1 = 0.f;
#pragma unroll
        for (int k = 0; k < 16; k += 2) {
            const float2 wa = zw_s[32 * k + lane];
            const float2 wb = zw_s[32 * (k + 1) + lane];
            p0 = fmaf(e[k],     wa.x, p0);  p1 = fmaf(e[k],     wa.y, p1);
            q0 = fmaf(e[k + 1], wb.x, q0);  q1 = fmaf(e[k + 1], wb.y, q1);
        }
        s_0 = p0 + q0;
        s_1 = p1 + q1;
    } else {
        // general path: per-channel length scales (correct for any sigma)
        s_0 = 0.f; s_1 = 0.f;
        float qv[4], wc0[4], wc1[4];
#pragma unroll
        for (int j = 0; j < 4; ++j) {
            const int c = lane + 32 * j;
            const float inv = __expf(-__ldg(sigma + c));
            qv[j]  = -0.5f * inv * inv;
            wc0[j] = __ldg(W + c);
            wc1[j] = __ldg(W + ZDIM + c);
        }
        for (int n = 0; n < NN; ++n) {
            const float d  = xm - __ldg(tg + n);
            const float d2 = d * d;
            const float* zr = z + (size_t)(b * NN + n) * ZDIM;
#pragma unroll
            for (int j = 0; j < 4; ++j) {
                const float ev = __ldg(zr + lane + 32 * j) * __expf(qv[j] * d2);
                s_0 = fmaf(ev, wc0[j], s_0);
                s_1 = fmaf(ev, wc1[j], s_1);
            }
        }
    }

    // ---- warp reduce + plain store (no atomics anywhere) ----
#pragma unroll
    for (int o = 16; o; o >>= 1) {
        s_0 += __shfl_xor_sync(0xFFFFFFFFu, s_0, o);
        s_1 += __shfl_xor_sync(0xFFFFFFFFu, s_1, o);
    }
    if (lane == 0)
        *(float2*)(out + 2 * (size_t)(b * MM + m)) = make_float2(s_0 + b0, s_1 + b1);
}

// ---------------------------------------------------------------------------
extern "C" void kernel_launch(void* const* d_in, const int* in_sizes, int n_in,
                              void* d_out, int out_size) {
    const float* t     = (const float*)d_in[0];
    const float* z     = (const float*)d_in[1];
    const float* x     = (const float*)d_in[2];
    const float* sigma = (const float*)d_in[3];
    const float* W     = (const float*)d_in[4];
    const float* bias  = (const float*)d_in[5];
    float* out = (float*)d_out;

    // compile-time cluster dims -> plain launch graph node
    decoder_final<<<GRID, NTHREADS>>>(t, z, x, sigma, W, bias, out);
}